// round 14
// baseline (speedup 1.0000x reference)
#include <cuda_runtime.h>
#include <cuda_fp16.h>
#include <cuda.h>
#include <cstdint>

#define B_  4
#define L_  4096
#define H_  16
#define D_  64
#define C_  1024
#define KNL 13
#define M_TOT (B_ * L_)          // 16384
#define K_TOT C_                 // 1024

typedef unsigned long long u64;

// ---------------- device scratch (no allocation allowed) ----------------
__device__ float g_q[(size_t)B_*H_*L_*D_];
__device__ float g_k[(size_t)B_*H_*L_*D_];
__device__ float g_v[(size_t)B_*H_*L_*D_];
__device__ __half g_x_h[(size_t)M_TOT*K_TOT];
__device__ __half g_att_h[(size_t)M_TOT*K_TOT];
__device__ __half g_wqkvT[(size_t)3*C_*C_];
__device__ __half g_wprojT[(size_t)C_*C_];

// ---------------- helpers ----------------
__device__ __forceinline__ uint32_t smem_u32(const void* p) {
    uint32_t a;
    asm("{ .reg .u64 t; cvta.to.shared.u64 t, %1; cvt.u32.u64 %0, t; }"
        : "=r"(a) : "l"(p));
    return a;
}
#define MBARRIER_INIT(addr, cnt) \
    asm volatile("mbarrier.init.shared.b64 [%0], %1;" :: "r"(addr), "r"(cnt) : "memory")
#define MBARRIER_EXPECT_TX(addr, bytes) \
    asm volatile("mbarrier.arrive.expect_tx.shared.b64 _, [%0], %1;" \
                 :: "r"(addr), "r"((uint32_t)(bytes)) : "memory")
#define MBARRIER_ARRIVE(addr) \
    asm volatile("mbarrier.arrive.release.cta.shared.b64 _, [%0];" :: "r"(addr) : "memory")
// bounded wait: never hangs the GPU; a stuck wait becomes a wrong answer.
__device__ __forceinline__ void mbar_wait(uint32_t mbar, uint32_t parity) {
    for (int it = 0; it < 65536; it++) {
        uint32_t done;
        asm volatile("{\n\t.reg .pred p;\n\t"
            "mbarrier.try_wait.parity.acquire.cta.shared::cta.b64 p, [%1], %2, 0x2710;\n\t"
            "selp.b32 %0, 1, 0, p;\n\t}"
            : "=r"(done) : "r"(mbar), "r"(parity) : "memory");
        if (done) return;
    }
}
#define FENCE_PROXY_ASYNC() asm volatile("fence.proxy.async.shared::cta;" ::: "memory")

__device__ __forceinline__ void tma2d(uint32_t dst, const void* map,
                                      int cx, int cy, uint32_t mbar) {
    asm volatile(
        "cp.async.bulk.tensor.2d.shared::cta.global.tile.mbarrier::complete_tx::bytes "
        "[%0], [%1, {%2, %3}], [%4];"
        :: "r"(dst), "l"(map), "r"(cx), "r"(cy), "r"(mbar) : "memory");
}

__device__ __forceinline__ void cpa16(uint32_t dst, const void* src) {
    asm volatile("cp.async.cg.shared.global [%0], [%1], 16;" :: "r"(dst), "l"(src));
}
#define CP_COMMIT() asm volatile("cp.async.commit_group;" ::: "memory")
#define CP_WAIT1()  asm volatile("cp.async.wait_group 1;" ::: "memory")

#define LDSM_X4(r, addr) \
    asm volatile("ldmatrix.sync.aligned.m8n8.x4.shared.b16 {%0,%1,%2,%3}, [%4];" \
        : "=r"((r)[0]), "=r"((r)[1]), "=r"((r)[2]), "=r"((r)[3]) : "r"(addr))

#define MMA_F16(acc, a, b0v, b1v) \
    asm volatile("mma.sync.aligned.m16n8k16.row.col.f32.f16.f16.f32 " \
        "{%0,%1,%2,%3},{%4,%5,%6,%7},{%8,%9},{%0,%1,%2,%3};" \
        : "+f"((acc)[0]), "+f"((acc)[1]), "+f"((acc)[2]), "+f"((acc)[3]) \
        : "r"((a)[0]), "r"((a)[1]), "r"((a)[2]), "r"((a)[3]), "r"(b0v), "r"(b1v))

__device__ __forceinline__ u64 bc2(float x) {
    u64 r; unsigned xi = __float_as_uint(x);
    asm("mov.b64 %0, {%1, %1};" : "=l"(r) : "r"(xi));
    return r;
}
__device__ __forceinline__ void fma2(u64& d, u64 a, u64 b) {
    asm("fma.rn.f32x2 %0, %1, %2, %0;" : "+l"(d) : "l"(a), "l"(b));
}
__device__ __forceinline__ float lo2(u64 v) { return __uint_as_float((unsigned)(v & 0xffffffffull)); }
__device__ __forceinline__ float hi2(u64 v) { return __uint_as_float((unsigned)(v >> 32)); }
__device__ __forceinline__ u64 pk2(float a, float b) {
    u64 r;
    asm("mov.b64 %0, {%1, %2};" : "=l"(r) : "r"(__float_as_uint(a)), "r"(__float_as_uint(b)));
    return r;
}

// ---------------- conversion kernels ----------------
__global__ __launch_bounds__(256) void convert_half_kernel(
    const float* __restrict__ src, __half* __restrict__ dst, size_t n4)
{
    size_t i = (size_t)blockIdx.x * 256 + threadIdx.x;
    if (i >= n4) return;
    float4 v = ((const float4*)src)[i];
    __half2 a = __floats2half2_rn(v.x, v.y);
    __half2 b = __floats2half2_rn(v.z, v.w);
    ((uint2*)dst)[i] = make_uint2(*(uint32_t*)&a, *(uint32_t*)&b);
}

// both weight transposes in one launch: z=0 -> w_qkv, z=1 -> w_proj (x<32)
__global__ __launch_bounds__(1024) void transpose_both_kernel(
    const float* __restrict__ wq, __half* __restrict__ tq,
    const float* __restrict__ wp, __half* __restrict__ tp)
{
    __shared__ float sm[32][33];
    int z = blockIdx.z;
    if (z == 1 && blockIdx.x >= 32) return;
    const float* w = (z == 0) ? wq : wp;
    __half* t      = (z == 0) ? tq : tp;
    int N = (z == 0) ? 3 * C_ : C_;
    int n0 = blockIdx.x * 32, k0 = blockIdx.y * 32;
    int tx = threadIdx.x, ty = threadIdx.y;
    sm[ty][tx] = w[(size_t)(k0 + ty) * N + n0 + tx];
    __syncthreads();
    t[(size_t)(n0 + ty) * C_ + k0 + tx] = __float2half_rn(sm[tx][ty]);
}

// ---------------- shared GEMM config ----------------
// CTA tile 128(M) x 128(N), 256 threads = 8 warps (2M x 4N), warp tile 64x32.
// Stage: A (128x64 fp16, 16K) @0 | B (128x64 fp16, 16K) @16K ; stride 32K.
// 3-slot single-chunk TMA pipeline; 2 CTAs / SM (regs exactly fill RF).
#define STG 32768
#define NSLOT 3
#define GEMM_SMEM_TMA (NSLOT * STG + 1024)     // 99,328 B -> 2 CTAs/SM
#define NSTG_CPA 3
#define CPA_STG 49152
#define GEMM_SMEM_CPA (NSTG_CPA * CPA_STG + 1024)
#define NCHUNK (K_TOT / 64)

extern __shared__ char gsm_raw[];

struct FragCtx {
    uint32_t xrA, xrB, aRowOff, bRowOff;
    int kbA, kbB;
};
__device__ __forceinline__ FragCtx frag_ctx(int lane, int warpM, int warpN) {
    FragCtx f;
    int g = lane >> 3, rr = lane & 7;
    int rA = (g & 1) * 8 + rr;
    f.kbA = (g >> 1) * 16;
    f.xrA = (uint32_t)((rA & 7) << 4);
    int rB = (g >> 1) * 8 + rr;
    f.kbB = (g & 1) * 16;
    f.xrB = (uint32_t)(rr << 4);
    f.aRowOff = (uint32_t)(warpM + rA) * 128;
    f.bRowOff = (uint32_t)(warpN + rB) * 128;
    return f;
}

__device__ __forceinline__ void compute_chunk(
    uint32_t sbase, const FragCtx& f, float acc[4][4][4])
{
    #pragma unroll
    for (int ks = 0; ks < 4; ks++) {
        uint32_t kterA = (uint32_t)((f.kbA + ks * 32)) ^ f.xrA;
        uint32_t kterB = (uint32_t)((f.kbB + ks * 32)) ^ f.xrB;
        uint32_t bh[2][4];
        #pragma unroll
        for (int jn = 0; jn < 2; jn++) {
            uint32_t bd = sbase + 16384 + f.bRowOff + (uint32_t)(jn * 2048) + kterB;
            LDSM_X4(bh[jn], bd);
        }
        #pragma unroll
        for (int im = 0; im < 4; im++) {
            uint32_t ah[4];
            uint32_t ad = sbase + f.aRowOff + (uint32_t)(im * 2048) + kterA;
            LDSM_X4(ah, ad);
            #pragma unroll
            for (int in = 0; in < 4; in++) {
                int jn = in >> 1, s = (in & 1) * 2;
                MMA_F16(acc[im][in], ah, bh[jn][s], bh[jn][s + 1]);
            }
        }
    }
}

__device__ __forceinline__ void gemm_epilogue(
    float acc[4][4][4], const float* bias, float* Cout,
    int m0, int n0, int warpM, int warpN, int lane, int Nt, int mode)
{
    int r0 = lane >> 2;
    int cp2 = (lane & 3) * 2;
    #pragma unroll
    for (int in = 0; in < 4; in++) {
        int n = n0 + warpN + in * 8 + cp2;
        float2 bs = *(const float2*)&bias[n];
        if (mode == 0) {
            int which = n >> 10, rem = n & 1023, h = rem >> 6, d = rem & 63;
            float scale = (which == 0) ? 0.125f : 1.0f;
            float* dst = (which == 0) ? g_q : (which == 1) ? g_k : g_v;
            #pragma unroll
            for (int im = 0; im < 4; im++) {
                #pragma unroll
                for (int half = 0; half < 2; half++) {
                    int m = m0 + warpM + im * 16 + r0 + half * 8;
                    int b = m >> 12, l = m & 4095;
                    float2 o;
                    o.x = (acc[im][in][half * 2 + 0] + bs.x) * scale;
                    o.y = (acc[im][in][half * 2 + 1] + bs.y) * scale;
                    *(float2*)&dst[(((size_t)(b * H_ + h)) * L_ + l) * D_ + d] = o;
                }
            }
        } else {
            #pragma unroll
            for (int im = 0; im < 4; im++) {
                #pragma unroll
                for (int half = 0; half < 2; half++) {
                    int m = m0 + warpM + im * 16 + r0 + half * 8;
                    float2 o;
                    o.x = acc[im][in][half * 2 + 0] + bs.x;
                    o.y = acc[im][in][half * 2 + 1] + bs.y;
                    *(float2*)&Cout[(size_t)m * Nt + n] = o;
                }
            }
        }
    }
}

// ---------------- persistent TMA GEMM (256 thr, 2 CTAs/SM) ----------------
__global__ __launch_bounds__(256, 2) void tma_gemm_kernel(
    const __grid_constant__ CUtensorMap mapA,
    const __grid_constant__ CUtensorMap mapB,
    const float* __restrict__ bias, float* __restrict__ Cout,
    int Nt, int mode, int ntiles)
{
    __shared__ __align__(8) unsigned long long s_full[NSLOT];
    __shared__ __align__(8) unsigned long long s_empty[NSLOT];

    int tid = threadIdx.x;
    int lane = tid & 31, wid = tid >> 5;
    int warpM = (wid & 1) * 64, warpN = (wid >> 1) * 32;
    int bid = blockIdx.x, NC = gridDim.x;
    int nx = Nt >> 7;                          // tiles along N (128-wide)

    int ntile = (ntiles - bid + NC - 1) / NC;
    if (ntile <= 0) return;
    int total = ntile * NCHUNK;                // chunk granularity

    uint32_t dynb = smem_u32(gsm_raw);
    uint32_t SB = (dynb + 1023) & ~1023u;

    if (tid == 0) {
        #pragma unroll
        for (int s = 0; s < NSLOT; s++) {
            MBARRIER_INIT(smem_u32(&s_full[s]), 1);
            MBARRIER_INIT(smem_u32(&s_empty[s]), 8);
        }
        FENCE_PROXY_ASYNC();
    }
    __syncthreads();

    auto issue_chunk = [&](int p) {
        int j = p >> 4, s = p & 15;
        int t = bid + j * NC;
        int m0 = (t / nx) * 128, n0 = (t % nx) * 128;
        int slot = p % NSLOT;
        uint32_t mb = smem_u32(&s_full[slot]);
        uint32_t dst = SB + (uint32_t)slot * STG;
        MBARRIER_EXPECT_TX(mb, STG);
        tma2d(dst,         &mapA, s * 64, m0, mb);
        tma2d(dst + 16384, &mapB, s * 64, n0, mb);
    };

    if (tid == 0) {
        issue_chunk(0);
        if (total > 1) issue_chunk(1);
    }

    FragCtx f = frag_ctx(lane, warpM, warpN);

    int c = 0;
    for (int j = 0; j < ntile; j++) {
        float acc[4][4][4];
        #pragma unroll
        for (int i = 0; i < 4; i++)
            #pragma unroll
            for (int jj = 0; jj < 4; jj++)
                #pragma unroll
                for (int q = 0; q < 4; q++) acc[i][jj][q] = 0.f;

        #pragma unroll 1
        for (int s = 0; s < NCHUNK; s++, c++) {
            int slot = c % NSLOT;
            mbar_wait(smem_u32(&s_full[slot]), (uint32_t)(c / NSLOT) & 1);
            compute_chunk(SB + (uint32_t)slot * STG, f, acc);
            if (lane == 0) MBARRIER_ARRIVE(smem_u32(&s_empty[slot]));
            if (tid == 0 && c + 2 < total) {
                int p = c + 2, ps = p % NSLOT;
                if (p >= NSLOT)
                    mbar_wait(smem_u32(&s_empty[ps]), (uint32_t)(p / NSLOT - 1) & 1);
                issue_chunk(p);
            }
        }

        int t = bid + j * NC;
        int m0 = (t / nx) * 128, n0 = (t % nx) * 128;
        gemm_epilogue(acc, bias, Cout, m0, n0, warpM, warpN, lane, Nt, mode);
    }
}

// ---------------- cp.async fallback GEMM (512 thr, tile 128x256) -------------
__device__ __forceinline__ void ld_stage_cpa(
    uint32_t sb, const __half* Ah, const __half* Bh,
    int m0, int n0, int kc, int tid)
{
    {
        int e = tid;
        int row = e >> 2, c16 = (e & 3) * 2;
        uint32_t off = row * 128 + c16 * 16;
        uint32_t sw0 = off ^ (uint32_t)((row & 7) << 4);
        uint32_t sw1 = (off + 16) ^ (uint32_t)((row & 7) << 4);
        size_t ga = (size_t)(m0 + row) * K_TOT + kc + c16 * 8;
        cpa16(sb + sw0, Ah + ga);
        cpa16(sb + sw1, Ah + ga + 8);
    }
    #pragma unroll
    for (int i = 0; i < 4; i++) {
        int e = tid + i * 512;
        int row = e >> 3, c16 = e & 7;
        uint32_t off = row * 128 + c16 * 16;
        uint32_t sw = off ^ (uint32_t)((row & 7) << 4);
        size_t gb = (size_t)(n0 + row) * K_TOT + kc + c16 * 8;
        cpa16(sb + 16384 + sw, Bh + gb);
    }
}

__global__ __launch_bounds__(512, 1) void cpa_gemm_kernel(
    const __half* __restrict__ Ah, const __half* __restrict__ Bh,
    const float* __restrict__ bias, float* __restrict__ Cout, int Nt, int mode)
{
    int tid = threadIdx.x;
    int lane = tid & 31, wid = tid >> 5;
    int m0 = blockIdx.y * 128, n0 = blockIdx.x * 256;
    int warpM = (wid & 1) * 64, warpN = (wid >> 1) * 32;

    uint32_t dynb = smem_u32(gsm_raw);
    uint32_t SB = (dynb + 1023) & ~1023u;

    FragCtx f = frag_ctx(lane, warpM, warpN);

    float acc[4][4][4];
    #pragma unroll
    for (int i = 0; i < 4; i++)
        #pragma unroll
        for (int j = 0; j < 4; j++)
            #pragma unroll
            for (int q = 0; q < 4; q++) acc[i][j][q] = 0.f;

    ld_stage_cpa(SB,           Ah, Bh, m0, n0, 0,  tid);
    CP_COMMIT();
    ld_stage_cpa(SB + CPA_STG, Ah, Bh, m0, n0, 64, tid);
    CP_COMMIT();

    int buf = 0;
    for (int c = 0; c < NCHUNK; c++) {
        CP_WAIT1();
        __syncthreads();
        if (c + 2 < NCHUNK) {
            int nb = buf + 2; if (nb >= NSTG_CPA) nb -= NSTG_CPA;
            ld_stage_cpa(SB + (uint32_t)nb * CPA_STG, Ah, Bh, m0, n0, (c + 2) * 64, tid);
        }
        CP_COMMIT();
        // fallback stage: B at +16KB within its 48KB stage (A 16K | B 32K)
        uint32_t sbase = SB + (uint32_t)buf * CPA_STG;
        #pragma unroll
        for (int ks = 0; ks < 4; ks++) {
            uint32_t kterA = (uint32_t)((f.kbA + ks * 32)) ^ f.xrA;
            uint32_t kterB = (uint32_t)((f.kbB + ks * 32)) ^ f.xrB;
            uint32_t bh[2][4];
            #pragma unroll
            for (int jn = 0; jn < 2; jn++) {
                uint32_t bd = sbase + 16384 + f.bRowOff + (uint32_t)(jn * 2048) + kterB;
                LDSM_X4(bh[jn], bd);
            }
            #pragma unroll
            for (int im = 0; im < 4; im++) {
                uint32_t ah[4];
                uint32_t ad = sbase + f.aRowOff + (uint32_t)(im * 2048) + kterA;
                LDSM_X4(ah, ad);
                #pragma unroll
                for (int in = 0; in < 4; in++) {
                    int jn = in >> 1, s = (in & 1) * 2;
                    MMA_F16(acc[im][in], ah, bh[jn][s], bh[jn][s + 1]);
                }
            }
        }
        buf++; if (buf >= NSTG_CPA) buf = 0;
    }

    gemm_epilogue(acc, bias, Cout, m0, n0, warpM, warpN, lane, Nt, mode);
}

// ---------------- neighborhood attention (float4 I/O, 3 CTAs/SM) -------------
#define LT  128
#define KVW 148
#define NA_COLS 144
#define QW  129
#define NA_SMEM ((64 * KVW + 64 * QW) * 4)

extern __shared__ float na_sm[];

__global__ __launch_bounds__(128) void na_kernel(const float* __restrict__ rpb)
{
    float* kv = na_sm;
    float* qo = na_sm + 64 * KVW;

    int tid = threadIdx.x;
    int n0 = blockIdx.x * LT;
    int bh = blockIdx.y;
    int h = bh & (H_ - 1);

    const float* kbase = g_k + (size_t)bh * L_ * D_;
    const float* vbase = g_v + (size_t)bh * L_ * D_;
    const float* qbase = g_q + (size_t)bh * L_ * D_;

    #pragma unroll 2
    for (int idx = tid; idx < NA_COLS * 16; idx += 128) {
        int col = idx >> 4, dq = idx & 15;
        int p = n0 - 6 + col;
        p = max(0, min(p, L_ - 1));
        float4 v = *(const float4*)(kbase + (size_t)p * 64 + dq * 4);
        float* c0 = &kv[(dq * 4) * KVW + col];
        c0[0] = v.x; c0[KVW] = v.y; c0[2 * KVW] = v.z; c0[3 * KVW] = v.w;
    }
    #pragma unroll 2
    for (int idx = tid; idx < LT * 16; idx += 128) {
        int l = idx >> 4, dq = idx & 15;
        float4 v = *(const float4*)(qbase + (size_t)(n0 + l) * 64 + dq * 4);
        float* c0 = &qo[(dq * 4) * QW + l];
        c0[0] = v.x; c0[QW] = v.y; c0[2 * QW] = v.z; c0[3 * QW] = v.w;
    }
    __syncthreads();

    int l = tid;
    int lg = n0 + l;
    int ni = max(0, min(lg - (KNL / 2), L_ - KNL));
    int col0 = ni - (n0 - 6);
    int wstart = col0 & ~3;
    int shift = col0 - wstart;

    u64 sw2[8];
    #pragma unroll
    for (int i = 0; i < 8; i++) sw2[i] = 0ull;

    for (int d = 0; d < 64; d++) {
        float qd = qo[d * QW + l];
        u64 q2 = bc2(qd);
        const ulonglong2* kr = (const ulonglong2*)&kv[d * KVW + wstart];
        ulonglong2 k01 = kr[0], k23 = kr[1], k45 = kr[2], k67 = kr[3];
        fma2(sw2[0], q2, k01.x); fma2(sw2[1], q2, k01.y);
        fma2(sw2[2], q2, k23.x); fma2(sw2[3], q2, k23.y);
        fma2(sw2[4], q2, k45.x); fma2(sw2[5], q2, k45.y);
        fma2(sw2[6], q2, k67.x); fma2(sw2[7], q2, k67.y);
    }

    float sw[16];
    #pragma unroll
    for (int i = 0; i < 8; i++) { sw[2 * i] = lo2(sw2[i]); sw[2 * i + 1] = hi2(sw2[i]); }

    int pb = h * (2 * KNL - 1) + (ni - lg + (KNL - 1));
    float mx = -1e30f;
    #pragma unroll
    for (int w = 0; w < 16; w++) {
        int bi = w - shift;
        bool inb = (bi >= 0) && (bi < KNL);
        sw[w] = inb ? (sw[w] + rpb[pb + (inb ? bi : 0)]) : -1e30f;
        mx = fmaxf(mx, sw[w]);
    }
    float sum = 0.f;
    #pragma unroll
    for (int w = 0; w < 16; w++) { sw[w] = __expf(sw[w] - mx); sum += sw[w]; }
    float inv = 1.f / sum;
    u64 p2[8];
    #pragma unroll
    for (int i = 0; i < 8; i++) p2[i] = pk2(sw[2 * i] * inv, sw[2 * i + 1] * inv);

    __syncthreads();
    #pragma unroll 2
    for (int idx = tid; idx < NA_COLS * 16; idx += 128) {
        int col = idx >> 4, dq = idx & 15;
        int p = n0 - 6 + col;
        p = max(0, min(p, L_ - 1));
        float4 v = *(const float4*)(vbase + (size_t)p * 64 + dq * 4);
        float* c0 = &kv[(dq * 4) * KVW + col];
        c0[0] = v.x; c0[KVW] = v.y; c0[2 * KVW] = v.z; c0[3 * KVW] = v.w;
    }
    __syncthreads();

    for (int d = 0; d < 64; d++) {
        const ulonglong2* vr = (const ulonglong2*)&kv[d * KVW + wstart];
        ulonglong2 v01 = vr[0], v23 = vr[1], v45 = vr[2], v67 = vr[3];
        u64 o2 = 0ull;
        fma2(o2, p2[0], v01.x); fma2(o2, p2[1], v01.y);
        fma2(o2, p2[2], v23.x); fma2(o2, p2[3], v23.y);
        fma2(o2, p2[4], v45.x); fma2(o2, p2[5], v45.y);
        fma2(o2, p2[6], v67.x); fma2(o2, p2[7], v67.y);
        qo[d * QW + l] = lo2(o2) + hi2(o2);
    }
    __syncthreads();

    int b = bh >> 4;
    size_t obase = ((size_t)b * L_ + n0) * C_ + h * 64;
    #pragma unroll 2
    for (int idx = tid; idx < LT * 16; idx += 128) {
        int l2 = idx >> 4, dq = idx & 15;
        const float* c0 = &qo[(dq * 4) * QW + l2];
        __half2 h0 = __floats2half2_rn(c0[0], c0[QW]);
        __half2 h1 = __floats2half2_rn(c0[2 * QW], c0[3 * QW]);
        *(uint2*)&g_att_h[obase + (size_t)l2 * C_ + dq * 4] =
            make_uint2(*(uint32_t*)&h0, *(uint32_t*)&h1);
    }
}

// ---------------- host: tensormap encode (guarded) ----------------
typedef CUresult (*PFN_encodeTiled)(
    CUtensorMap*, CUtensorMapDataType, cuuint32_t, void*,
    const cuuint64_t*, const cuuint64_t*, const cuuint32_t*, const cuuint32_t*,
    CUtensorMapInterleave, CUtensorMapSwizzle, CUtensorMapL2promotion,
    CUtensorMapFloatOOBfill);

static bool make_map(PFN_encodeTiled fn, CUtensorMap* m, void* base,
                     uint64_t rows, uint32_t boxRows) {
    if (!fn) return false;
    cuuint64_t dims[2]    = {(cuuint64_t)K_TOT, (cuuint64_t)rows};
    cuuint64_t strides[1] = {(cuuint64_t)K_TOT * 2};
    cuuint32_t box[2]     = {64, boxRows};
    cuuint32_t es[2]      = {1, 1};
    CUresult r = fn(m, CU_TENSOR_MAP_DATA_TYPE_FLOAT16, 2, base,
                    dims, strides, box, es,
                    CU_TENSOR_MAP_INTERLEAVE_NONE, CU_TENSOR_MAP_SWIZZLE_128B,
                    CU_TENSOR_MAP_L2_PROMOTION_L2_128B,
                    CU_TENSOR_MAP_FLOAT_OOB_FILL_NONE);
    return r == CUDA_SUCCESS;
}

// ---------------- launch ----------------
extern "C" void kernel_launch(void* const* d_in, const int* in_sizes, int n_in,
                              void* d_out, int out_size)
{
    const float* x      = (const float*)d_in[0];
    const float* w_qkv  = (const float*)d_in[1];
    const float* b_qkv  = (const float*)d_in[2];
    const float* rpb    = (const float*)d_in[3];
    const float* w_proj = (const float*)d_in[4];
    const float* b_proj = (const float*)d_in[5];
    float* out = (float*)d_out;

    static bool attr_set = false;
    static int n_sm = 148;
    if (!attr_set) {
        cudaFuncSetAttribute(na_kernel, cudaFuncAttributeMaxDynamicSharedMemorySize, NA_SMEM);
        cudaFuncSetAttribute(tma_gemm_kernel, cudaFuncAttributeMaxDynamicSharedMemorySize, GEMM_SMEM_TMA);
        cudaFuncSetAttribute(cpa_gemm_kernel, cudaFuncAttributeMaxDynamicSharedMemorySize, GEMM_SMEM_CPA);
        cudaDeviceGetAttribute(&n_sm, cudaDevAttrMultiProcessorCount, 0);
        if (n_sm <= 0) n_sm = 148;
        attr_set = true;
    }

    __half *xh, *ath, *wq, *wp;
    cudaGetSymbolAddress((void**)&xh,  g_x_h);
    cudaGetSymbolAddress((void**)&ath, g_att_h);
    cudaGetSymbolAddress((void**)&wq,  g_wqkvT);
    cudaGetSymbolAddress((void**)&wp,  g_wprojT);

    static PFN_encodeTiled enc = nullptr;
    static bool enc_tried = false;
    if (!enc_tried) {
        enc_tried = true;
        void* p = nullptr;
        cudaDriverEntryPointQueryResult qr = cudaDriverEntryPointSuccess;
        cudaError_t e = cudaGetDriverEntryPoint("cuTensorMapEncodeTiled", &p,
                                                cudaEnableDefault, &qr);
        if (e == cudaSuccess && qr == cudaDriverEntryPointSuccess && p)
            enc = (PFN_encodeTiled)p;
        else
            cudaGetLastError();
    }

    CUtensorMap mapX, mapAtt, mapWq, mapWp;
    bool use_tma = true;
    use_tma &= make_map(enc, &mapX,   xh,  M_TOT,  128);
    use_tma &= make_map(enc, &mapAtt, ath, M_TOT,  128);
    use_tma &= make_map(enc, &mapWq,  wq,  3 * C_, 128);
    use_tma &= make_map(enc, &mapWp,  wp,  C_,     128);

    size_t n4 = (size_t)M_TOT * K_TOT / 4;
    convert_half_kernel<<<(unsigned)((n4 + 255) / 256), 256>>>(x, xh, n4);

    transpose_both_kernel<<<dim3(3 * C_ / 32, C_ / 32, 2), dim3(32, 32)>>>(
        w_qkv, wq, w_proj, wp);

    const int tilesQ = (3 * C_ / 128) * (M_TOT / 128);   // 3072
    const int tilesP = (C_ / 128) * (M_TOT / 128);       // 1024

    if (use_tma)
        tma_gemm_kernel<<<min(2 * n_sm, tilesQ), 256, GEMM_SMEM_TMA>>>(
            mapX, mapWq, b_qkv, out, 3 * C_, 0, tilesQ);
    else
        cpa_gemm_kernel<<<dim3(3 * C_ / 256, M_TOT / 128), 512, GEMM_SMEM_CPA>>>(
            xh, wq, b_qkv, out, 3 * C_, 0);

    na_kernel<<<dim3(L_ / LT, B_ * H_), 128, NA_SMEM>>>(rpb);

    if (use_tma)
        tma_gemm_kernel<<<min(2 * n_sm, tilesP), 256, GEMM_SMEM_TMA>>>(
            mapAtt, mapWp, b_proj, out, C_, 1, tilesP);
    else
        cpa_gemm_kernel<<<dim3(C_ / 256, M_TOT / 128), 512, GEMM_SMEM_CPA>>>(
            ath, wp, b_proj, out, C_, 1);
}

// round 15
// speedup vs baseline: 1.0153x; 1.0153x over previous
#include <cuda_runtime.h>
#include <cuda_fp16.h>
#include <cuda.h>
#include <cstdint>

#define B_  4
#define L_  4096
#define H_  16
#define D_  64
#define C_  1024
#define KNL 13
#define M_TOT (B_ * L_)          // 16384
#define K_TOT C_                 // 1024

typedef unsigned long long u64;

// ---------------- device scratch (no allocation allowed) ----------------
__device__ float g_q[(size_t)B_*H_*L_*D_];
__device__ float g_k[(size_t)B_*H_*L_*D_];
__device__ float g_v[(size_t)B_*H_*L_*D_];
__device__ __half g_x_h[(size_t)M_TOT*K_TOT];
__device__ __half g_att_h[(size_t)M_TOT*K_TOT];
__device__ __half g_wqkvT[(size_t)3*C_*C_];
__device__ __half g_wprojT[(size_t)C_*C_];

// ---------------- helpers ----------------
__device__ __forceinline__ uint32_t smem_u32(const void* p) {
    uint32_t a;
    asm("{ .reg .u64 t; cvta.to.shared.u64 t, %1; cvt.u32.u64 %0, t; }"
        : "=r"(a) : "l"(p));
    return a;
}
#define MBARRIER_INIT(addr, cnt) \
    asm volatile("mbarrier.init.shared.b64 [%0], %1;" :: "r"(addr), "r"(cnt) : "memory")
#define MBARRIER_EXPECT_TX(addr, bytes) \
    asm volatile("mbarrier.arrive.expect_tx.shared.b64 _, [%0], %1;" \
                 :: "r"(addr), "r"((uint32_t)(bytes)) : "memory")
#define MBARRIER_ARRIVE(addr) \
    asm volatile("mbarrier.arrive.release.cta.shared.b64 _, [%0];" :: "r"(addr) : "memory")
__device__ __forceinline__ void mbar_wait(uint32_t mbar, uint32_t parity) {
    for (int it = 0; it < 65536; it++) {
        uint32_t done;
        asm volatile("{\n\t.reg .pred p;\n\t"
            "mbarrier.try_wait.parity.acquire.cta.shared::cta.b64 p, [%1], %2, 0x2710;\n\t"
            "selp.b32 %0, 1, 0, p;\n\t}"
            : "=r"(done) : "r"(mbar), "r"(parity) : "memory");
        if (done) return;
    }
}
#define FENCE_PROXY_ASYNC() asm volatile("fence.proxy.async.shared::cta;" ::: "memory")

__device__ __forceinline__ void tma2d(uint32_t dst, const void* map,
                                      int cx, int cy, uint32_t mbar) {
    asm volatile(
        "cp.async.bulk.tensor.2d.shared::cta.global.tile.mbarrier::complete_tx::bytes "
        "[%0], [%1, {%2, %3}], [%4];"
        :: "r"(dst), "l"(map), "r"(cx), "r"(cy), "r"(mbar) : "memory");
}

__device__ __forceinline__ void cpa16(uint32_t dst, const void* src) {
    asm volatile("cp.async.cg.shared.global [%0], [%1], 16;" :: "r"(dst), "l"(src));
}
#define CP_COMMIT() asm volatile("cp.async.commit_group;" ::: "memory")
#define CP_WAIT1()  asm volatile("cp.async.wait_group 1;" ::: "memory")

#define LDSM_X4(r, addr) \
    asm volatile("ldmatrix.sync.aligned.m8n8.x4.shared.b16 {%0,%1,%2,%3}, [%4];" \
        : "=r"((r)[0]), "=r"((r)[1]), "=r"((r)[2]), "=r"((r)[3]) : "r"(addr))

#define MMA_F16(acc, a, b0v, b1v) \
    asm volatile("mma.sync.aligned.m16n8k16.row.col.f32.f16.f16.f32 " \
        "{%0,%1,%2,%3},{%4,%5,%6,%7},{%8,%9},{%0,%1,%2,%3};" \
        : "+f"((acc)[0]), "+f"((acc)[1]), "+f"((acc)[2]), "+f"((acc)[3]) \
        : "r"((a)[0]), "r"((a)[1]), "r"((a)[2]), "r"((a)[3]), "r"(b0v), "r"(b1v))

__device__ __forceinline__ u64 bc2(float x) {
    u64 r; unsigned xi = __float_as_uint(x);
    asm("mov.b64 %0, {%1, %1};" : "=l"(r) : "r"(xi));
    return r;
}
__device__ __forceinline__ void fma2(u64& d, u64 a, u64 b) {
    asm("fma.rn.f32x2 %0, %1, %2, %0;" : "+l"(d) : "l"(a), "l"(b));
}
__device__ __forceinline__ u64 add2(u64 a, u64 b) {
    u64 r;
    asm("add.rn.f32x2 %0, %1, %2;" : "=l"(r) : "l"(a), "l"(b));
    return r;
}
__device__ __forceinline__ float lo2(u64 v) { return __uint_as_float((unsigned)(v & 0xffffffffull)); }
__device__ __forceinline__ float hi2(u64 v) { return __uint_as_float((unsigned)(v >> 32)); }
__device__ __forceinline__ u64 pk2(float a, float b) {
    u64 r;
    asm("mov.b64 %0, {%1, %2};" : "=l"(r) : "r"(__float_as_uint(a)), "r"(__float_as_uint(b)));
    return r;
}

// ---------------- conversion kernels ----------------
__global__ __launch_bounds__(256) void convert_half_kernel(
    const float* __restrict__ src, __half* __restrict__ dst, size_t n4)
{
    size_t i = (size_t)blockIdx.x * 256 + threadIdx.x;
    if (i >= n4) return;
    float4 v = ((const float4*)src)[i];
    __half2 a = __floats2half2_rn(v.x, v.y);
    __half2 b = __floats2half2_rn(v.z, v.w);
    ((uint2*)dst)[i] = make_uint2(*(uint32_t*)&a, *(uint32_t*)&b);
}

// both weight transposes in one launch: z=0 -> w_qkv, z=1 -> w_proj (x<32)
__global__ __launch_bounds__(1024) void transpose_both_kernel(
    const float* __restrict__ wq, __half* __restrict__ tq,
    const float* __restrict__ wp, __half* __restrict__ tp)
{
    __shared__ float sm[32][33];
    int z = blockIdx.z;
    if (z == 1 && blockIdx.x >= 32) return;
    const float* w = (z == 0) ? wq : wp;
    __half* t      = (z == 0) ? tq : tp;
    int N = (z == 0) ? 3 * C_ : C_;
    int n0 = blockIdx.x * 32, k0 = blockIdx.y * 32;
    int tx = threadIdx.x, ty = threadIdx.y;
    sm[ty][tx] = w[(size_t)(k0 + ty) * N + n0 + tx];
    __syncthreads();
    t[(size_t)(n0 + ty) * C_ + k0 + tx] = __float2half_rn(sm[tx][ty]);
}

// ---------------- shared GEMM config (R13 winner) ----------------
// CTA tile 128(M) x 256(N), 512 threads = 16 warps (2M x 8N), warp tile 64x32.
// Stage: A (128x64 fp16, 16K) @0 | B (256x64 fp16, 32K) @16K ; stride 48K.
// Persistent CTAs; 4 slots = 2 super-stages (2 chunks / mbarrier).
#define STG 49152
#define NSLOT 4
#define GEMM_SMEM_TMA (NSLOT * STG + 1024)
#define NSTG_CPA 3
#define GEMM_SMEM_CPA (NSTG_CPA * STG + 1024)
#define NCHUNK (K_TOT / 64)
#define SUP_PER_TILE 8

extern __shared__ char gsm_raw[];

struct FragCtx {
    uint32_t xrA, xrB, aRowOff, bRowOff;
    int kbA, kbB;
};
__device__ __forceinline__ FragCtx frag_ctx(int lane, int warpM, int warpN) {
    FragCtx f;
    int g = lane >> 3, rr = lane & 7;
    int rA = (g & 1) * 8 + rr;
    f.kbA = (g >> 1) * 16;
    f.xrA = (uint32_t)((rA & 7) << 4);
    int rB = (g >> 1) * 8 + rr;
    f.kbB = (g & 1) * 16;
    f.xrB = (uint32_t)(rr << 4);
    f.aRowOff = (uint32_t)(warpM + rA) * 128;
    f.bRowOff = (uint32_t)(warpN + rB) * 128;
    return f;
}

__device__ __forceinline__ void compute_chunk(
    uint32_t sbase, const FragCtx& f, float acc[4][4][4])
{
    #pragma unroll
    for (int ks = 0; ks < 4; ks++) {
        uint32_t kterA = (uint32_t)((f.kbA + ks * 32)) ^ f.xrA;
        uint32_t kterB = (uint32_t)((f.kbB + ks * 32)) ^ f.xrB;
        uint32_t bh[2][4];
        #pragma unroll
        for (int jn = 0; jn < 2; jn++) {
            uint32_t bd = sbase + 16384 + f.bRowOff + (uint32_t)(jn * 2048) + kterB;
            LDSM_X4(bh[jn], bd);
        }
        #pragma unroll
        for (int im = 0; im < 4; im++) {
            uint32_t ah[4];
            uint32_t ad = sbase + f.aRowOff + (uint32_t)(im * 2048) + kterA;
            LDSM_X4(ah, ad);
            #pragma unroll
            for (int in = 0; in < 4; in++) {
                int jn = in >> 1, s = (in & 1) * 2;
                MMA_F16(acc[im][in], ah, bh[jn][s], bh[jn][s + 1]);
            }
        }
    }
}

__device__ __forceinline__ void gemm_epilogue(
    float acc[4][4][4], const float* bias, float* Cout,
    int m0, int n0, int warpM, int warpN, int lane, int Nt, int mode)
{
    int r0 = lane >> 2;
    int cp2 = (lane & 3) * 2;
    #pragma unroll
    for (int in = 0; in < 4; in++) {
        int n = n0 + warpN + in * 8 + cp2;
        float2 bs = *(const float2*)&bias[n];
        if (mode == 0) {
            int which = n >> 10, rem = n & 1023, h = rem >> 6, d = rem & 63;
            float scale = (which == 0) ? 0.125f : 1.0f;
            float* dst = (which == 0) ? g_q : (which == 1) ? g_k : g_v;
            #pragma unroll
            for (int im = 0; im < 4; im++) {
                #pragma unroll
                for (int half = 0; half < 2; half++) {
                    int m = m0 + warpM + im * 16 + r0 + half * 8;
                    int b = m >> 12, l = m & 4095;
                    float2 o;
                    o.x = (acc[im][in][half * 2 + 0] + bs.x) * scale;
                    o.y = (acc[im][in][half * 2 + 1] + bs.y) * scale;
                    *(float2*)&dst[(((size_t)(b * H_ + h)) * L_ + l) * D_ + d] = o;
                }
            }
        } else {
            #pragma unroll
            for (int im = 0; im < 4; im++) {
                #pragma unroll
                for (int half = 0; half < 2; half++) {
                    int m = m0 + warpM + im * 16 + r0 + half * 8;
                    float2 o;
                    o.x = acc[im][in][half * 2 + 0] + bs.x;
                    o.y = acc[im][in][half * 2 + 1] + bs.y;
                    *(float2*)&Cout[(size_t)m * Nt + n] = o;
                }
            }
        }
    }
}

// ---------------- persistent TMA GEMM (R13) ----------------
__global__ __launch_bounds__(512, 1) void tma_gemm_kernel(
    const __grid_constant__ CUtensorMap mapA,
    const __grid_constant__ CUtensorMap mapB,
    const float* __restrict__ bias, float* __restrict__ Cout,
    int Nt, int mode, int ntiles)
{
    __shared__ __align__(8) unsigned long long s_full[2];
    __shared__ __align__(8) unsigned long long s_empty[2];

    int tid = threadIdx.x;
    int lane = tid & 31, wid = tid >> 5;
    int warpM = (wid & 1) * 64, warpN = (wid >> 1) * 32;
    int bid = blockIdx.x, NC = gridDim.x;
    int nx = Nt >> 8;

    int ntile = (ntiles - bid + NC - 1) / NC;
    if (ntile <= 0) return;
    int total = ntile * SUP_PER_TILE;

    uint32_t dynb = smem_u32(gsm_raw);
    uint32_t SB = (dynb + 1023) & ~1023u;

    if (tid == 0) {
        #pragma unroll
        for (int s = 0; s < 2; s++) {
            MBARRIER_INIT(smem_u32(&s_full[s]), 1);
            MBARRIER_INIT(smem_u32(&s_empty[s]), 16);
        }
        FENCE_PROXY_ASYNC();
    }
    __syncthreads();

    auto issue_super = [&](int g) {
        int j = g >> 3, s = g & 7;
        int t = bid + j * NC;
        int m0 = (t / nx) * 128, n0 = (t % nx) * 256;
        int b = g & 1;
        uint32_t mb = smem_u32(&s_full[b]);
        MBARRIER_EXPECT_TX(mb, 2 * STG);
        #pragma unroll
        for (int hh = 0; hh < 2; hh++) {
            int chunk = s * 2 + hh;
            uint32_t dst = SB + (uint32_t)(2 * b + hh) * STG;
            tma2d(dst,         &mapA, chunk * 64, m0, mb);
            tma2d(dst + 16384, &mapB, chunk * 64, n0, mb);
        }
    };

    if (tid == 0) {
        issue_super(0);
        if (total > 1) issue_super(1);
    }

    FragCtx f = frag_ctx(lane, warpM, warpN);

    int g = 0;
    for (int j = 0; j < ntile; j++) {
        float acc[4][4][4];
        #pragma unroll
        for (int i = 0; i < 4; i++)
            #pragma unroll
            for (int jj = 0; jj < 4; jj++)
                #pragma unroll
                for (int q = 0; q < 4; q++) acc[i][jj][q] = 0.f;

        #pragma unroll 1
        for (int s = 0; s < SUP_PER_TILE; s++, g++) {
            int b = g & 1;
            uint32_t par = (uint32_t)(g >> 1) & 1;
            mbar_wait(smem_u32(&s_full[b]), par);
            uint32_t base = SB + (uint32_t)(2 * b) * STG;
            compute_chunk(base,       f, acc);
            compute_chunk(base + STG, f, acc);
            if (lane == 0) MBARRIER_ARRIVE(smem_u32(&s_empty[b]));
            if (tid == 0 && g + 2 < total) {
                mbar_wait(smem_u32(&s_empty[b]), par);
                issue_super(g + 2);
            }
        }

        int t = bid + j * NC;
        int m0 = (t / nx) * 128, n0 = (t % nx) * 256;
        gemm_epilogue(acc, bias, Cout, m0, n0, warpM, warpN, lane, Nt, mode);
    }
}

// ---------------- cp.async fallback GEMM ----------------
__device__ __forceinline__ void ld_stage_cpa(
    uint32_t sb, const __half* Ah, const __half* Bh,
    int m0, int n0, int kc, int tid)
{
    {
        int e = tid;
        int row = e >> 2, c16 = (e & 3) * 2;
        uint32_t off = row * 128 + c16 * 16;
        uint32_t sw0 = off ^ (uint32_t)((row & 7) << 4);
        uint32_t sw1 = (off + 16) ^ (uint32_t)((row & 7) << 4);
        size_t ga = (size_t)(m0 + row) * K_TOT + kc + c16 * 8;
        cpa16(sb + sw0, Ah + ga);
        cpa16(sb + sw1, Ah + ga + 8);
    }
    #pragma unroll
    for (int i = 0; i < 4; i++) {
        int e = tid + i * 512;
        int row = e >> 3, c16 = e & 7;
        uint32_t off = row * 128 + c16 * 16;
        uint32_t sw = off ^ (uint32_t)((row & 7) << 4);
        size_t gb = (size_t)(n0 + row) * K_TOT + kc + c16 * 8;
        cpa16(sb + 16384 + sw, Bh + gb);
    }
}

__global__ __launch_bounds__(512, 1) void cpa_gemm_kernel(
    const __half* __restrict__ Ah, const __half* __restrict__ Bh,
    const float* __restrict__ bias, float* __restrict__ Cout, int Nt, int mode)
{
    int tid = threadIdx.x;
    int lane = tid & 31, wid = tid >> 5;
    int m0 = blockIdx.y * 128, n0 = blockIdx.x * 256;
    int warpM = (wid & 1) * 64, warpN = (wid >> 1) * 32;

    uint32_t dynb = smem_u32(gsm_raw);
    uint32_t SB = (dynb + 1023) & ~1023u;

    FragCtx f = frag_ctx(lane, warpM, warpN);

    float acc[4][4][4];
    #pragma unroll
    for (int i = 0; i < 4; i++)
        #pragma unroll
        for (int j = 0; j < 4; j++)
            #pragma unroll
            for (int q = 0; q < 4; q++) acc[i][j][q] = 0.f;

    ld_stage_cpa(SB,       Ah, Bh, m0, n0, 0,  tid);
    CP_COMMIT();
    ld_stage_cpa(SB + STG, Ah, Bh, m0, n0, 64, tid);
    CP_COMMIT();

    int buf = 0;
    for (int c = 0; c < NCHUNK; c++) {
        CP_WAIT1();
        __syncthreads();
        if (c + 2 < NCHUNK) {
            int nb = buf + 2; if (nb >= NSTG_CPA) nb -= NSTG_CPA;
            ld_stage_cpa(SB + (uint32_t)nb * STG, Ah, Bh, m0, n0, (c + 2) * 64, tid);
        }
        CP_COMMIT();
        compute_chunk(SB + (uint32_t)buf * STG, f, acc);
        buf++; if (buf >= NSTG_CPA) buf = 0;
    }

    gemm_epilogue(acc, bias, Cout, m0, n0, warpM, warpN, lane, Nt, mode);
}

// ---------------- neighborhood attention (256 thr, pair-split d) -------------
#define LT  128
#define KVW 148
#define NA_COLS 144
#define QW  129
#define NA_SMEM ((64 * KVW + 64 * QW) * 4)   // ~71KB -> 3 CTAs/SM, 24 warps

extern __shared__ float na_sm[];

__global__ __launch_bounds__(256) void na_kernel(const float* __restrict__ rpb)
{
    float* kv = na_sm;
    float* qo = na_sm + 64 * KVW;

    int tid = threadIdx.x;
    int n0 = blockIdx.x * LT;
    int bh = blockIdx.y;
    int h = bh & (H_ - 1);

    const float* kbase = g_k + (size_t)bh * L_ * D_;
    const float* vbase = g_v + (size_t)bh * L_ * D_;
    const float* qbase = g_q + (size_t)bh * L_ * D_;

    #pragma unroll 2
    for (int idx = tid; idx < NA_COLS * 16; idx += 256) {
        int col = idx >> 4, dq = idx & 15;
        int p = n0 - 6 + col;
        p = max(0, min(p, L_ - 1));
        float4 v = *(const float4*)(kbase + (size_t)p * 64 + dq * 4);
        float* c0 = &kv[(dq * 4) * KVW + col];
        c0[0] = v.x; c0[KVW] = v.y; c0[2 * KVW] = v.z; c0[3 * KVW] = v.w;
    }
    #pragma unroll 2
    for (int idx = tid; idx < LT * 16; idx += 256) {
        int l = idx >> 4, dq = idx & 15;
        float4 v = *(const float4*)(qbase + (size_t)(n0 + l) * 64 + dq * 4);
        float* c0 = &qo[(dq * 4) * QW + l];
        c0[0] = v.x; c0[QW] = v.y; c0[2 * QW] = v.z; c0[3 * QW] = v.w;
    }
    __syncthreads();

    int l = tid >> 1;                  // position 0..127
    int dhalf = tid & 1;               // pair lane: d-range half
    int d0 = dhalf * 32;
    int lg = n0 + l;
    int ni = max(0, min(lg - (KNL / 2), L_ - KNL));
    int col0 = ni - (n0 - 6);
    int wstart = col0 & ~3;
    int shift = col0 - wstart;

    u64 sw2[8];
    #pragma unroll
    for (int i = 0; i < 8; i++) sw2[i] = 0ull;

    for (int d = d0; d < d0 + 32; d++) {
        float qd = qo[d * QW + l];
        u64 q2 = bc2(qd);
        const ulonglong2* kr = (const ulonglong2*)&kv[d * KVW + wstart];
        ulonglong2 k01 = kr[0], k23 = kr[1], k45 = kr[2], k67 = kr[3];
        fma2(sw2[0], q2, k01.x); fma2(sw2[1], q2, k01.y);
        fma2(sw2[2], q2, k23.x); fma2(sw2[3], q2, k23.y);
        fma2(sw2[4], q2, k45.x); fma2(sw2[5], q2, k45.y);
        fma2(sw2[6], q2, k67.x); fma2(sw2[7], q2, k67.y);
    }
    // combine pair halves (adjacent lanes, same warp)
    #pragma unroll
    for (int i = 0; i < 8; i++)
        sw2[i] = add2(sw2[i], __shfl_xor_sync(0xFFFFFFFFu, sw2[i], 1));

    float sw[16];
    #pragma unroll
    for (int i = 0; i < 8; i++) { sw[2 * i] = lo2(sw2[i]); sw[2 * i + 1] = hi2(sw2[i]); }

    int pb = h * (2 * KNL - 1) + (ni - lg + (KNL - 1));
    float mx = -1e30f;
    #pragma unroll
    for (int w = 0; w < 16; w++) {
        int bi = w - shift;
        bool inb = (bi >= 0) && (bi < KNL);
        sw[w] = inb ? (sw[w] + rpb[pb + (inb ? bi : 0)]) : -1e30f;
        mx = fmaxf(mx, sw[w]);
    }
    float sum = 0.f;
    #pragma unroll
    for (int w = 0; w < 16; w++) { sw[w] = __expf(sw[w] - mx); sum += sw[w]; }
    float inv = 1.f / sum;
    u64 p2[8];
    #pragma unroll
    for (int i = 0; i < 8; i++) p2[i] = pk2(sw[2 * i] * inv, sw[2 * i + 1] * inv);

    __syncthreads();
    #pragma unroll 2
    for (int idx = tid; idx < NA_COLS * 16; idx += 256) {
        int col = idx >> 4, dq = idx & 15;
        int p = n0 - 6 + col;
        p = max(0, min(p, L_ - 1));
        float4 v = *(const float4*)(vbase + (size_t)p * 64 + dq * 4);
        float* c0 = &kv[(dq * 4) * KVW + col];
        c0[0] = v.x; c0[KVW] = v.y; c0[2 * KVW] = v.z; c0[3 * KVW] = v.w;
    }
    __syncthreads();

    for (int d = d0; d < d0 + 32; d++) {
        const ulonglong2* vr = (const ulonglong2*)&kv[d * KVW + wstart];
        ulonglong2 v01 = vr[0], v23 = vr[1], v45 = vr[2], v67 = vr[3];
        u64 o2 = 0ull;
        fma2(o2, p2[0], v01.x); fma2(o2, p2[1], v01.y);
        fma2(o2, p2[2], v23.x); fma2(o2, p2[3], v23.y);
        fma2(o2, p2[4], v45.x); fma2(o2, p2[5], v45.y);
        fma2(o2, p2[6], v67.x); fma2(o2, p2[7], v67.y);
        qo[d * QW + l] = lo2(o2) + hi2(o2);
    }
    __syncthreads();

    int b = bh >> 4;
    size_t obase = ((size_t)b * L_ + n0) * C_ + h * 64;
    #pragma unroll 2
    for (int idx = tid; idx < LT * 16; idx += 256) {
        int l2 = idx >> 4, dq = idx & 15;
        const float* c0 = &qo[(dq * 4) * QW + l2];
        __half2 h0 = __floats2half2_rn(c0[0], c0[QW]);
        __half2 h1 = __floats2half2_rn(c0[2 * QW], c0[3 * QW]);
        *(uint2*)&g_att_h[obase + (size_t)l2 * C_ + dq * 4] =
            make_uint2(*(uint32_t*)&h0, *(uint32_t*)&h1);
    }
}

// ---------------- host: tensormap encode (guarded) ----------------
typedef CUresult (*PFN_encodeTiled)(
    CUtensorMap*, CUtensorMapDataType, cuuint32_t, void*,
    const cuuint64_t*, const cuuint64_t*, const cuuint32_t*, const cuuint32_t*,
    CUtensorMapInterleave, CUtensorMapSwizzle, CUtensorMapL2promotion,
    CUtensorMapFloatOOBfill);

static bool make_map(PFN_encodeTiled fn, CUtensorMap* m, void* base,
                     uint64_t rows, uint32_t boxRows) {
    if (!fn) return false;
    cuuint64_t dims[2]    = {(cuuint64_t)K_TOT, (cuuint64_t)rows};
    cuuint64_t strides[1] = {(cuuint64_t)K_TOT * 2};
    cuuint32_t box[2]     = {64, boxRows};
    cuuint32_t es[2]      = {1, 1};
    CUresult r = fn(m, CU_TENSOR_MAP_DATA_TYPE_FLOAT16, 2, base,
                    dims, strides, box, es,
                    CU_TENSOR_MAP_INTERLEAVE_NONE, CU_TENSOR_MAP_SWIZZLE_128B,
                    CU_TENSOR_MAP_L2_PROMOTION_L2_128B,
                    CU_TENSOR_MAP_FLOAT_OOB_FILL_NONE);
    return r == CUDA_SUCCESS;
}

// ---------------- launch ----------------
extern "C" void kernel_launch(void* const* d_in, const int* in_sizes, int n_in,
                              void* d_out, int out_size)
{
    const float* x      = (const float*)d_in[0];
    const float* w_qkv  = (const float*)d_in[1];
    const float* b_qkv  = (const float*)d_in[2];
    const float* rpb    = (const float*)d_in[3];
    const float* w_proj = (const float*)d_in[4];
    const float* b_proj = (const float*)d_in[5];
    float* out = (float*)d_out;

    static bool attr_set = false;
    static int n_sm = 148;
    if (!attr_set) {
        cudaFuncSetAttribute(na_kernel, cudaFuncAttributeMaxDynamicSharedMemorySize, NA_SMEM);
        cudaFuncSetAttribute(tma_gemm_kernel, cudaFuncAttributeMaxDynamicSharedMemorySize, GEMM_SMEM_TMA);
        cudaFuncSetAttribute(cpa_gemm_kernel, cudaFuncAttributeMaxDynamicSharedMemorySize, GEMM_SMEM_CPA);
        cudaDeviceGetAttribute(&n_sm, cudaDevAttrMultiProcessorCount, 0);
        if (n_sm <= 0) n_sm = 148;
        attr_set = true;
    }

    __half *xh, *ath, *wq, *wp;
    cudaGetSymbolAddress((void**)&xh,  g_x_h);
    cudaGetSymbolAddress((void**)&ath, g_att_h);
    cudaGetSymbolAddress((void**)&wq,  g_wqkvT);
    cudaGetSymbolAddress((void**)&wp,  g_wprojT);

    static PFN_encodeTiled enc = nullptr;
    static bool enc_tried = false;
    if (!enc_tried) {
        enc_tried = true;
        void* p = nullptr;
        cudaDriverEntryPointQueryResult qr = cudaDriverEntryPointSuccess;
        cudaError_t e = cudaGetDriverEntryPoint("cuTensorMapEncodeTiled", &p,
                                                cudaEnableDefault, &qr);
        if (e == cudaSuccess && qr == cudaDriverEntryPointSuccess && p)
            enc = (PFN_encodeTiled)p;
        else
            cudaGetLastError();
    }

    CUtensorMap mapX, mapAtt, mapWq, mapWp;
    bool use_tma = true;
    use_tma &= make_map(enc, &mapX,   xh,  M_TOT,  128);
    use_tma &= make_map(enc, &mapAtt, ath, M_TOT,  128);
    use_tma &= make_map(enc, &mapWq,  wq,  3 * C_, 256);
    use_tma &= make_map(enc, &mapWp,  wp,  C_,     256);

    size_t n4 = (size_t)M_TOT * K_TOT / 4;
    convert_half_kernel<<<(unsigned)((n4 + 255) / 256), 256>>>(x, xh, n4);

    transpose_both_kernel<<<dim3(3 * C_ / 32, C_ / 32, 2), dim3(32, 32)>>>(
        w_qkv, wq, w_proj, wp);

    const int tilesQ = (3 * C_ / 256) * (M_TOT / 128);   // 1536
    const int tilesP = (C_ / 256) * (M_TOT / 128);       // 512

    if (use_tma)
        tma_gemm_kernel<<<min(n_sm, tilesQ), 512, GEMM_SMEM_TMA>>>(
            mapX, mapWq, b_qkv, out, 3 * C_, 0, tilesQ);
    else
        cpa_gemm_kernel<<<dim3(3 * C_ / 256, M_TOT / 128), 512, GEMM_SMEM_CPA>>>(
            xh, wq, b_qkv, out, 3 * C_, 0);

    na_kernel<<<dim3(L_ / LT, B_ * H_), 256, NA_SMEM>>>(rpb);

    if (use_tma)
        tma_gemm_kernel<<<min(n_sm, tilesP), 512, GEMM_SMEM_TMA>>>(
            mapAtt, mapWp, b_proj, out, C_, 1, tilesP);
    else
        cpa_gemm_kernel<<<dim3(C_ / 256, M_TOT / 128), 512, GEMM_SMEM_CPA>>>(
            ath, wp, b_proj, out, C_, 1);
}

// round 16
// speedup vs baseline: 1.0672x; 1.0512x over previous
#include <cuda_runtime.h>
#include <cuda_fp16.h>
#include <cuda.h>
#include <cstdint>

#define B_  4
#define L_  4096
#define H_  16
#define D_  64
#define C_  1024
#define KNL 13
#define M_TOT (B_ * L_)          // 16384
#define K_TOT C_                 // 1024

typedef unsigned long long u64;

// ---------------- device scratch (no allocation allowed) ----------------
__device__ float g_q[(size_t)B_*H_*L_*D_];
__device__ float g_k[(size_t)B_*H_*L_*D_];
__device__ float g_v[(size_t)B_*H_*L_*D_];
__device__ __half g_x_h[(size_t)M_TOT*K_TOT];
__device__ __half g_att_h[(size_t)M_TOT*K_TOT];
__device__ __half g_wqkvT[(size_t)3*C_*C_];
__device__ __half g_wprojT[(size_t)C_*C_];

// ---------------- helpers ----------------
__device__ __forceinline__ uint32_t smem_u32(const void* p) {
    uint32_t a;
    asm("{ .reg .u64 t; cvta.to.shared.u64 t, %1; cvt.u32.u64 %0, t; }"
        : "=r"(a) : "l"(p));
    return a;
}
#define MBARRIER_INIT(addr, cnt) \
    asm volatile("mbarrier.init.shared.b64 [%0], %1;" :: "r"(addr), "r"(cnt) : "memory")
#define MBARRIER_EXPECT_TX(addr, bytes) \
    asm volatile("mbarrier.arrive.expect_tx.shared.b64 _, [%0], %1;" \
                 :: "r"(addr), "r"((uint32_t)(bytes)) : "memory")
#define MBARRIER_ARRIVE(addr) \
    asm volatile("mbarrier.arrive.release.cta.shared.b64 _, [%0];" :: "r"(addr) : "memory")
__device__ __forceinline__ void mbar_wait(uint32_t mbar, uint32_t parity) {
    for (int it = 0; it < 65536; it++) {
        uint32_t done;
        asm volatile("{\n\t.reg .pred p;\n\t"
            "mbarrier.try_wait.parity.acquire.cta.shared::cta.b64 p, [%1], %2, 0x2710;\n\t"
            "selp.b32 %0, 1, 0, p;\n\t}"
            : "=r"(done) : "r"(mbar), "r"(parity) : "memory");
        if (done) return;
    }
}
#define FENCE_PROXY_ASYNC() asm volatile("fence.proxy.async.shared::cta;" ::: "memory")

__device__ __forceinline__ void tma2d(uint32_t dst, const void* map,
                                      int cx, int cy, uint32_t mbar) {
    asm volatile(
        "cp.async.bulk.tensor.2d.shared::cta.global.tile.mbarrier::complete_tx::bytes "
        "[%0], [%1, {%2, %3}], [%4];"
        :: "r"(dst), "l"(map), "r"(cx), "r"(cy), "r"(mbar) : "memory");
}

__device__ __forceinline__ void cpa16(uint32_t dst, const void* src) {
    asm volatile("cp.async.cg.shared.global [%0], [%1], 16;" :: "r"(dst), "l"(src));
}
#define CP_COMMIT() asm volatile("cp.async.commit_group;" ::: "memory")
#define CP_WAIT1()  asm volatile("cp.async.wait_group 1;" ::: "memory")

#define LDSM_X4(r, addr) \
    asm volatile("ldmatrix.sync.aligned.m8n8.x4.shared.b16 {%0,%1,%2,%3}, [%4];" \
        : "=r"((r)[0]), "=r"((r)[1]), "=r"((r)[2]), "=r"((r)[3]) : "r"(addr))

#define MMA_F16(acc, a, b0v, b1v) \
    asm volatile("mma.sync.aligned.m16n8k16.row.col.f32.f16.f16.f32 " \
        "{%0,%1,%2,%3},{%4,%5,%6,%7},{%8,%9},{%0,%1,%2,%3};" \
        : "+f"((acc)[0]), "+f"((acc)[1]), "+f"((acc)[2]), "+f"((acc)[3]) \
        : "r"((a)[0]), "r"((a)[1]), "r"((a)[2]), "r"((a)[3]), "r"(b0v), "r"(b1v))

__device__ __forceinline__ u64 bc2(float x) {
    u64 r; unsigned xi = __float_as_uint(x);
    asm("mov.b64 %0, {%1, %1};" : "=l"(r) : "r"(xi));
    return r;
}
__device__ __forceinline__ void fma2(u64& d, u64 a, u64 b) {
    asm("fma.rn.f32x2 %0, %1, %2, %0;" : "+l"(d) : "l"(a), "l"(b));
}
__device__ __forceinline__ u64 add2(u64 a, u64 b) {
    u64 r;
    asm("add.rn.f32x2 %0, %1, %2;" : "=l"(r) : "l"(a), "l"(b));
    return r;
}
__device__ __forceinline__ float lo2(u64 v) { return __uint_as_float((unsigned)(v & 0xffffffffull)); }
__device__ __forceinline__ float hi2(u64 v) { return __uint_as_float((unsigned)(v >> 32)); }
__device__ __forceinline__ u64 pk2(float a, float b) {
    u64 r;
    asm("mov.b64 %0, {%1, %2};" : "=l"(r) : "r"(__float_as_uint(a)), "r"(__float_as_uint(b)));
    return r;
}

// ---------------- conversion kernels ----------------
__global__ __launch_bounds__(256) void convert_half_kernel(
    const float* __restrict__ src, __half* __restrict__ dst, size_t n4)
{
    size_t i = (size_t)blockIdx.x * 256 + threadIdx.x;
    if (i >= n4) return;
    float4 v = ((const float4*)src)[i];
    __half2 a = __floats2half2_rn(v.x, v.y);
    __half2 b = __floats2half2_rn(v.z, v.w);
    ((uint2*)dst)[i] = make_uint2(*(uint32_t*)&a, *(uint32_t*)&b);
}

// both weight transposes in one launch: z=0 -> w_qkv, z=1 -> w_proj (x<32)
__global__ __launch_bounds__(1024) void transpose_both_kernel(
    const float* __restrict__ wq, __half* __restrict__ tq,
    const float* __restrict__ wp, __half* __restrict__ tp)
{
    __shared__ float sm[32][33];
    int z = blockIdx.z;
    if (z == 1 && blockIdx.x >= 32) return;
    const float* w = (z == 0) ? wq : wp;
    __half* t      = (z == 0) ? tq : tp;
    int N = (z == 0) ? 3 * C_ : C_;
    int n0 = blockIdx.x * 32, k0 = blockIdx.y * 32;
    int tx = threadIdx.x, ty = threadIdx.y;
    sm[ty][tx] = w[(size_t)(k0 + ty) * N + n0 + tx];
    __syncthreads();
    t[(size_t)(n0 + ty) * C_ + k0 + tx] = __float2half_rn(sm[tx][ty]);
}

// ---------------- shared GEMM config (R13 winner) ----------------
// CTA tile 128(M) x 256(N), 512 threads = 16 warps (2M x 8N), warp tile 64x32.
// Stage: A (128x64 fp16, 16K) @0 | B (256x64 fp16, 32K) @16K ; stride 48K.
// Persistent CTAs; 4 slots = 2 super-stages (2 chunks / mbarrier).
#define STG 49152
#define NSLOT 4
#define GEMM_SMEM_TMA (NSLOT * STG + 1024)
#define NSTG_CPA 3
#define GEMM_SMEM_CPA (NSTG_CPA * STG + 1024)
#define NCHUNK (K_TOT / 64)
#define SUP_PER_TILE 8

extern __shared__ char gsm_raw[];

struct FragCtx {
    uint32_t xrA, xrB, aRowOff, bRowOff;
    int kbA, kbB;
};
__device__ __forceinline__ FragCtx frag_ctx(int lane, int warpM, int warpN) {
    FragCtx f;
    int g = lane >> 3, rr = lane & 7;
    int rA = (g & 1) * 8 + rr;
    f.kbA = (g >> 1) * 16;
    f.xrA = (uint32_t)((rA & 7) << 4);
    int rB = (g >> 1) * 8 + rr;
    f.kbB = (g & 1) * 16;
    f.xrB = (uint32_t)(rr << 4);
    f.aRowOff = (uint32_t)(warpM + rA) * 128;
    f.bRowOff = (uint32_t)(warpN + rB) * 128;
    return f;
}

__device__ __forceinline__ void compute_chunk(
    uint32_t sbase, const FragCtx& f, float acc[4][4][4])
{
    #pragma unroll
    for (int ks = 0; ks < 4; ks++) {
        uint32_t kterA = (uint32_t)((f.kbA + ks * 32)) ^ f.xrA;
        uint32_t kterB = (uint32_t)((f.kbB + ks * 32)) ^ f.xrB;
        uint32_t bh[2][4];
        #pragma unroll
        for (int jn = 0; jn < 2; jn++) {
            uint32_t bd = sbase + 16384 + f.bRowOff + (uint32_t)(jn * 2048) + kterB;
            LDSM_X4(bh[jn], bd);
        }
        #pragma unroll
        for (int im = 0; im < 4; im++) {
            uint32_t ah[4];
            uint32_t ad = sbase + f.aRowOff + (uint32_t)(im * 2048) + kterA;
            LDSM_X4(ah, ad);
            #pragma unroll
            for (int in = 0; in < 4; in++) {
                int jn = in >> 1, s = (in & 1) * 2;
                MMA_F16(acc[im][in], ah, bh[jn][s], bh[jn][s + 1]);
            }
        }
    }
}

__device__ __forceinline__ void gemm_epilogue(
    float acc[4][4][4], const float* bias, float* Cout,
    int m0, int n0, int warpM, int warpN, int lane, int Nt, int mode)
{
    int r0 = lane >> 2;
    int cp2 = (lane & 3) * 2;
    #pragma unroll
    for (int in = 0; in < 4; in++) {
        int n = n0 + warpN + in * 8 + cp2;
        float2 bs = *(const float2*)&bias[n];
        if (mode == 0) {
            int which = n >> 10, rem = n & 1023, h = rem >> 6, d = rem & 63;
            float scale = (which == 0) ? 0.125f : 1.0f;
            float* dst = (which == 0) ? g_q : (which == 1) ? g_k : g_v;
            #pragma unroll
            for (int im = 0; im < 4; im++) {
                #pragma unroll
                for (int half = 0; half < 2; half++) {
                    int m = m0 + warpM + im * 16 + r0 + half * 8;
                    int b = m >> 12, l = m & 4095;
                    float2 o;
                    o.x = (acc[im][in][half * 2 + 0] + bs.x) * scale;
                    o.y = (acc[im][in][half * 2 + 1] + bs.y) * scale;
                    *(float2*)&dst[(((size_t)(b * H_ + h)) * L_ + l) * D_ + d] = o;
                }
            }
        } else {
            #pragma unroll
            for (int im = 0; im < 4; im++) {
                #pragma unroll
                for (int half = 0; half < 2; half++) {
                    int m = m0 + warpM + im * 16 + r0 + half * 8;
                    float2 o;
                    o.x = acc[im][in][half * 2 + 0] + bs.x;
                    o.y = acc[im][in][half * 2 + 1] + bs.y;
                    *(float2*)&Cout[(size_t)m * Nt + n] = o;
                }
            }
        }
    }
}

// ---------------- persistent TMA GEMM (R13) ----------------
__global__ __launch_bounds__(512, 1) void tma_gemm_kernel(
    const __grid_constant__ CUtensorMap mapA,
    const __grid_constant__ CUtensorMap mapB,
    const float* __restrict__ bias, float* __restrict__ Cout,
    int Nt, int mode, int ntiles)
{
    __shared__ __align__(8) unsigned long long s_full[2];
    __shared__ __align__(8) unsigned long long s_empty[2];

    int tid = threadIdx.x;
    int lane = tid & 31, wid = tid >> 5;
    int warpM = (wid & 1) * 64, warpN = (wid >> 1) * 32;
    int bid = blockIdx.x, NC = gridDim.x;
    int nx = Nt >> 8;

    int ntile = (ntiles - bid + NC - 1) / NC;
    if (ntile <= 0) return;
    int total = ntile * SUP_PER_TILE;

    uint32_t dynb = smem_u32(gsm_raw);
    uint32_t SB = (dynb + 1023) & ~1023u;

    if (tid == 0) {
        #pragma unroll
        for (int s = 0; s < 2; s++) {
            MBARRIER_INIT(smem_u32(&s_full[s]), 1);
            MBARRIER_INIT(smem_u32(&s_empty[s]), 16);
        }
        FENCE_PROXY_ASYNC();
    }
    __syncthreads();

    auto issue_super = [&](int g) {
        int j = g >> 3, s = g & 7;
        int t = bid + j * NC;
        int m0 = (t / nx) * 128, n0 = (t % nx) * 256;
        int b = g & 1;
        uint32_t mb = smem_u32(&s_full[b]);
        MBARRIER_EXPECT_TX(mb, 2 * STG);
        #pragma unroll
        for (int hh = 0; hh < 2; hh++) {
            int chunk = s * 2 + hh;
            uint32_t dst = SB + (uint32_t)(2 * b + hh) * STG;
            tma2d(dst,         &mapA, chunk * 64, m0, mb);
            tma2d(dst + 16384, &mapB, chunk * 64, n0, mb);
        }
    };

    if (tid == 0) {
        issue_super(0);
        if (total > 1) issue_super(1);
    }

    FragCtx f = frag_ctx(lane, warpM, warpN);

    int g = 0;
    for (int j = 0; j < ntile; j++) {
        float acc[4][4][4];
        #pragma unroll
        for (int i = 0; i < 4; i++)
            #pragma unroll
            for (int jj = 0; jj < 4; jj++)
                #pragma unroll
                for (int q = 0; q < 4; q++) acc[i][jj][q] = 0.f;

        #pragma unroll 1
        for (int s = 0; s < SUP_PER_TILE; s++, g++) {
            int b = g & 1;
            uint32_t par = (uint32_t)(g >> 1) & 1;
            mbar_wait(smem_u32(&s_full[b]), par);
            uint32_t base = SB + (uint32_t)(2 * b) * STG;
            compute_chunk(base,       f, acc);
            compute_chunk(base + STG, f, acc);
            if (lane == 0) MBARRIER_ARRIVE(smem_u32(&s_empty[b]));
            if (tid == 0 && g + 2 < total) {
                mbar_wait(smem_u32(&s_empty[b]), par);
                issue_super(g + 2);
            }
        }

        int t = bid + j * NC;
        int m0 = (t / nx) * 128, n0 = (t % nx) * 256;
        gemm_epilogue(acc, bias, Cout, m0, n0, warpM, warpN, lane, Nt, mode);
    }
}

// ---------------- cp.async fallback GEMM ----------------
__device__ __forceinline__ void ld_stage_cpa(
    uint32_t sb, const __half* Ah, const __half* Bh,
    int m0, int n0, int kc, int tid)
{
    {
        int e = tid;
        int row = e >> 2, c16 = (e & 3) * 2;
        uint32_t off = row * 128 + c16 * 16;
        uint32_t sw0 = off ^ (uint32_t)((row & 7) << 4);
        uint32_t sw1 = (off + 16) ^ (uint32_t)((row & 7) << 4);
        size_t ga = (size_t)(m0 + row) * K_TOT + kc + c16 * 8;
        cpa16(sb + sw0, Ah + ga);
        cpa16(sb + sw1, Ah + ga + 8);
    }
    #pragma unroll
    for (int i = 0; i < 4; i++) {
        int e = tid + i * 512;
        int row = e >> 3, c16 = e & 7;
        uint32_t off = row * 128 + c16 * 16;
        uint32_t sw = off ^ (uint32_t)((row & 7) << 4);
        size_t gb = (size_t)(n0 + row) * K_TOT + kc + c16 * 8;
        cpa16(sb + 16384 + sw, Bh + gb);
    }
}

__global__ __launch_bounds__(512, 1) void cpa_gemm_kernel(
    const __half* __restrict__ Ah, const __half* __restrict__ Bh,
    const float* __restrict__ bias, float* __restrict__ Cout, int Nt, int mode)
{
    int tid = threadIdx.x;
    int lane = tid & 31, wid = tid >> 5;
    int m0 = blockIdx.y * 128, n0 = blockIdx.x * 256;
    int warpM = (wid & 1) * 64, warpN = (wid >> 1) * 32;

    uint32_t dynb = smem_u32(gsm_raw);
    uint32_t SB = (dynb + 1023) & ~1023u;

    FragCtx f = frag_ctx(lane, warpM, warpN);

    float acc[4][4][4];
    #pragma unroll
    for (int i = 0; i < 4; i++)
        #pragma unroll
        for (int j = 0; j < 4; j++)
            #pragma unroll
            for (int q = 0; q < 4; q++) acc[i][j][q] = 0.f;

    ld_stage_cpa(SB,       Ah, Bh, m0, n0, 0,  tid);
    CP_COMMIT();
    ld_stage_cpa(SB + STG, Ah, Bh, m0, n0, 64, tid);
    CP_COMMIT();

    int buf = 0;
    for (int c = 0; c < NCHUNK; c++) {
        CP_WAIT1();
        __syncthreads();
        if (c + 2 < NCHUNK) {
            int nb = buf + 2; if (nb >= NSTG_CPA) nb -= NSTG_CPA;
            ld_stage_cpa(SB + (uint32_t)nb * STG, Ah, Bh, m0, n0, (c + 2) * 64, tid);
        }
        CP_COMMIT();
        compute_chunk(SB + (uint32_t)buf * STG, f, acc);
        buf++; if (buf >= NSTG_CPA) buf = 0;
    }

    gemm_epilogue(acc, bias, Cout, m0, n0, warpM, warpN, lane, Nt, mode);
}

// ---------------- neighborhood attention (256 thr, interleaved pair-d) -------
#define LT  128
#define KVW 148
#define NA_COLS 144
#define QW  129
#define NA_SMEM ((64 * KVW + 64 * QW) * 4)   // ~71KB -> 3 CTAs/SM, 24 warps

extern __shared__ float na_sm[];

__global__ __launch_bounds__(256) void na_kernel(const float* __restrict__ rpb)
{
    float* kv = na_sm;
    float* qo = na_sm + 64 * KVW;

    int tid = threadIdx.x;
    int n0 = blockIdx.x * LT;
    int bh = blockIdx.y;
    int h = bh & (H_ - 1);

    const float* kbase = g_k + (size_t)bh * L_ * D_;
    const float* vbase = g_v + (size_t)bh * L_ * D_;
    const float* qbase = g_q + (size_t)bh * L_ * D_;

    #pragma unroll 2
    for (int idx = tid; idx < NA_COLS * 16; idx += 256) {
        int col = idx >> 4, dq = idx & 15;
        int p = n0 - 6 + col;
        p = max(0, min(p, L_ - 1));
        float4 v = *(const float4*)(kbase + (size_t)p * 64 + dq * 4);
        float* c0 = &kv[(dq * 4) * KVW + col];
        c0[0] = v.x; c0[KVW] = v.y; c0[2 * KVW] = v.z; c0[3 * KVW] = v.w;
    }
    #pragma unroll 2
    for (int idx = tid; idx < LT * 16; idx += 256) {
        int l = idx >> 4, dq = idx & 15;
        float4 v = *(const float4*)(qbase + (size_t)(n0 + l) * 64 + dq * 4);
        float* c0 = &qo[(dq * 4) * QW + l];
        c0[0] = v.x; c0[QW] = v.y; c0[2 * QW] = v.z; c0[3 * QW] = v.w;
    }
    __syncthreads();

    int l = tid >> 1;                  // position 0..127
    int dhalf = tid & 1;               // pair lane: interleaved d parity
    int lg = n0 + l;
    int ni = max(0, min(lg - (KNL / 2), L_ - KNL));
    int col0 = ni - (n0 - 6);
    int wstart = col0 & ~3;
    int shift = col0 - wstart;

    u64 sw2[8];
    #pragma unroll
    for (int i = 0; i < 8; i++) sw2[i] = 0ull;

    // pair lanes take d = dhalf, dhalf+2, ... -> row offsets differ by KVW
    // (148 mod 32 = 20) -> disjoint bank groups, conflict-free.
    for (int d = dhalf; d < 64; d += 2) {
        float qd = qo[d * QW + l];
        u64 q2 = bc2(qd);
        const ulonglong2* kr = (const ulonglong2*)&kv[d * KVW + wstart];
        ulonglong2 k01 = kr[0], k23 = kr[1], k45 = kr[2], k67 = kr[3];
        fma2(sw2[0], q2, k01.x); fma2(sw2[1], q2, k01.y);
        fma2(sw2[2], q2, k23.x); fma2(sw2[3], q2, k23.y);
        fma2(sw2[4], q2, k45.x); fma2(sw2[5], q2, k45.y);
        fma2(sw2[6], q2, k67.x); fma2(sw2[7], q2, k67.y);
    }
    // combine pair halves (adjacent lanes, same warp)
    #pragma unroll
    for (int i = 0; i < 8; i++)
        sw2[i] = add2(sw2[i], __shfl_xor_sync(0xFFFFFFFFu, sw2[i], 1));

    float sw[16];
    #pragma unroll
    for (int i = 0; i < 8; i++) { sw[2 * i] = lo2(sw2[i]); sw[2 * i + 1] = hi2(sw2[i]); }

    int pb = h * (2 * KNL - 1) + (ni - lg + (KNL - 1));
    float mx = -1e30f;
    #pragma unroll
    for (int w = 0; w < 16; w++) {
        int bi = w - shift;
        bool inb = (bi >= 0) && (bi < KNL);
        sw[w] = inb ? (sw[w] + rpb[pb + (inb ? bi : 0)]) : -1e30f;
        mx = fmaxf(mx, sw[w]);
    }
    float sum = 0.f;
    #pragma unroll
    for (int w = 0; w < 16; w++) { sw[w] = __expf(sw[w] - mx); sum += sw[w]; }
    float inv = 1.f / sum;
    u64 p2[8];
    #pragma unroll
    for (int i = 0; i < 8; i++) p2[i] = pk2(sw[2 * i] * inv, sw[2 * i + 1] * inv);

    __syncthreads();
    #pragma unroll 2
    for (int idx = tid; idx < NA_COLS * 16; idx += 256) {
        int col = idx >> 4, dq = idx & 15;
        int p = n0 - 6 + col;
        p = max(0, min(p, L_ - 1));
        float4 v = *(const float4*)(vbase + (size_t)p * 64 + dq * 4);
        float* c0 = &kv[(dq * 4) * KVW + col];
        c0[0] = v.x; c0[KVW] = v.y; c0[2 * KVW] = v.z; c0[3 * KVW] = v.w;
    }
    __syncthreads();

    for (int d = dhalf; d < 64; d += 2) {
        const ulonglong2* vr = (const ulonglong2*)&kv[d * KVW + wstart];
        ulonglong2 v01 = vr[0], v23 = vr[1], v45 = vr[2], v67 = vr[3];
        u64 o2 = 0ull;
        fma2(o2, p2[0], v01.x); fma2(o2, p2[1], v01.y);
        fma2(o2, p2[2], v23.x); fma2(o2, p2[3], v23.y);
        fma2(o2, p2[4], v45.x); fma2(o2, p2[5], v45.y);
        fma2(o2, p2[6], v67.x); fma2(o2, p2[7], v67.y);
        qo[d * QW + l] = lo2(o2) + hi2(o2);
    }
    __syncthreads();

    int b = bh >> 4;
    size_t obase = ((size_t)b * L_ + n0) * C_ + h * 64;
    #pragma unroll 2
    for (int idx = tid; idx < LT * 16; idx += 256) {
        int l2 = idx >> 4, dq = idx & 15;
        const float* c0 = &qo[(dq * 4) * QW + l2];
        __half2 h0 = __floats2half2_rn(c0[0], c0[QW]);
        __half2 h1 = __floats2half2_rn(c0[2 * QW], c0[3 * QW]);
        *(uint2*)&g_att_h[obase + (size_t)l2 * C_ + dq * 4] =
            make_uint2(*(uint32_t*)&h0, *(uint32_t*)&h1);
    }
}

// ---------------- host: tensormap encode (guarded) ----------------
typedef CUresult (*PFN_encodeTiled)(
    CUtensorMap*, CUtensorMapDataType, cuuint32_t, void*,
    const cuuint64_t*, const cuuint64_t*, const cuuint32_t*, const cuuint32_t*,
    CUtensorMapInterleave, CUtensorMapSwizzle, CUtensorMapL2promotion,
    CUtensorMapFloatOOBfill);

static bool make_map(PFN_encodeTiled fn, CUtensorMap* m, void* base,
                     uint64_t rows, uint32_t boxRows) {
    if (!fn) return false;
    cuuint64_t dims[2]    = {(cuuint64_t)K_TOT, (cuuint64_t)rows};
    cuuint64_t strides[1] = {(cuuint64_t)K_TOT * 2};
    cuuint32_t box[2]     = {64, boxRows};
    cuuint32_t es[2]      = {1, 1};
    CUresult r = fn(m, CU_TENSOR_MAP_DATA_TYPE_FLOAT16, 2, base,
                    dims, strides, box, es,
                    CU_TENSOR_MAP_INTERLEAVE_NONE, CU_TENSOR_MAP_SWIZZLE_128B,
                    CU_TENSOR_MAP_L2_PROMOTION_L2_128B,
                    CU_TENSOR_MAP_FLOAT_OOB_FILL_NONE);
    return r == CUDA_SUCCESS;
}

// ---------------- launch ----------------
extern "C" void kernel_launch(void* const* d_in, const int* in_sizes, int n_in,
                              void* d_out, int out_size)
{
    const float* x      = (const float*)d_in[0];
    const float* w_qkv  = (const float*)d_in[1];
    const float* b_qkv  = (const float*)d_in[2];
    const float* rpb    = (const float*)d_in[3];
    const float* w_proj = (const float*)d_in[4];
    const float* b_proj = (const float*)d_in[5];
    float* out = (float*)d_out;

    static bool attr_set = false;
    static int n_sm = 148;
    if (!attr_set) {
        cudaFuncSetAttribute(na_kernel, cudaFuncAttributeMaxDynamicSharedMemorySize, NA_SMEM);
        cudaFuncSetAttribute(tma_gemm_kernel, cudaFuncAttributeMaxDynamicSharedMemorySize, GEMM_SMEM_TMA);
        cudaFuncSetAttribute(cpa_gemm_kernel, cudaFuncAttributeMaxDynamicSharedMemorySize, GEMM_SMEM_CPA);
        cudaDeviceGetAttribute(&n_sm, cudaDevAttrMultiProcessorCount, 0);
        if (n_sm <= 0) n_sm = 148;
        attr_set = true;
    }

    __half *xh, *ath, *wq, *wp;
    cudaGetSymbolAddress((void**)&xh,  g_x_h);
    cudaGetSymbolAddress((void**)&ath, g_att_h);
    cudaGetSymbolAddress((void**)&wq,  g_wqkvT);
    cudaGetSymbolAddress((void**)&wp,  g_wprojT);

    static PFN_encodeTiled enc = nullptr;
    static bool enc_tried = false;
    if (!enc_tried) {
        enc_tried = true;
        void* p = nullptr;
        cudaDriverEntryPointQueryResult qr = cudaDriverEntryPointSuccess;
        cudaError_t e = cudaGetDriverEntryPoint("cuTensorMapEncodeTiled", &p,
                                                cudaEnableDefault, &qr);
        if (e == cudaSuccess && qr == cudaDriverEntryPointSuccess && p)
            enc = (PFN_encodeTiled)p;
        else
            cudaGetLastError();
    }

    CUtensorMap mapX, mapAtt, mapWq, mapWp;
    bool use_tma = true;
    use_tma &= make_map(enc, &mapX,   xh,  M_TOT,  128);
    use_tma &= make_map(enc, &mapAtt, ath, M_TOT,  128);
    use_tma &= make_map(enc, &mapWq,  wq,  3 * C_, 256);
    use_tma &= make_map(enc, &mapWp,  wp,  C_,     256);

    size_t n4 = (size_t)M_TOT * K_TOT / 4;
    convert_half_kernel<<<(unsigned)((n4 + 255) / 256), 256>>>(x, xh, n4);

    transpose_both_kernel<<<dim3(3 * C_ / 32, C_ / 32, 2), dim3(32, 32)>>>(
        w_qkv, wq, w_proj, wp);

    const int tilesQ = (3 * C_ / 256) * (M_TOT / 128);   // 1536
    const int tilesP = (C_ / 256) * (M_TOT / 128);       // 512

    if (use_tma)
        tma_gemm_kernel<<<min(n_sm, tilesQ), 512, GEMM_SMEM_TMA>>>(
            mapX, mapWq, b_qkv, out, 3 * C_, 0, tilesQ);
    else
        cpa_gemm_kernel<<<dim3(3 * C_ / 256, M_TOT / 128), 512, GEMM_SMEM_CPA>>>(
            xh, wq, b_qkv, out, 3 * C_, 0);

    na_kernel<<<dim3(L_ / LT, B_ * H_), 256, NA_SMEM>>>(rpb);

    if (use_tma)
        tma_gemm_kernel<<<min(n_sm, tilesP), 512, GEMM_SMEM_TMA>>>(
            mapAtt, mapWp, b_proj, out, C_, 1, tilesP);
    else
        cpa_gemm_kernel<<<dim3(C_ / 256, M_TOT / 128), 512, GEMM_SMEM_CPA>>>(
            ath, wp, b_proj, out, C_, 1);
}